// round 2
// baseline (speedup 1.0000x reference)
#include <cuda_runtime.h>
#include <math.h>

#define HID 128
#define MAX_N 100352
#define MAXSTEPS 8
#define NG 256

// ---------------- scratch (static device globals; no runtime allocation) ----
__device__ __align__(16) float g_h   [MAX_N * HID];        // hidden state [N,128]
__device__ __align__(16) float g_out1[MAX_N * 512];        // [m(128) | gh(384)] per node
__device__ __align__(16) float g_agg [MAX_N * HID];        // scatter-add target
__device__ __align__(16) float g_gi  [MAX_N * 384];        // GRU input gates
__device__ __align__(16) float g_Wcat[MAXSTEPS * HID * 512]; // [W_mpnn[s] | w_hh^T]
__device__ __align__(16) float g_WihT[HID * 384];          // w_ih^T
__device__ __align__(16) float g_sums[NG * HID];
__device__ __align__(16) float g_cnt [NG];

// ---------------- utility kernels ------------------------------------------
__global__ void zero_kernel(float* p, long long n) {
    long long i = (long long)blockIdx.x * blockDim.x + threadIdx.x;
    long long stride = (long long)gridDim.x * blockDim.x;
    for (; i < n; i += stride) p[i] = 0.0f;
}

__global__ void pack_wcat_kernel(const float* __restrict__ Wm,
                                 const float* __restrict__ whh,
                                 float* __restrict__ Wcat, int steps) {
    int idx = blockIdx.x * blockDim.x + threadIdx.x;
    int total = steps * HID * 512;
    if (idx >= total) return;
    int s = idx / (HID * 512);
    int rem = idx % (HID * 512);
    int k = rem / 512;
    int j = rem % 512;
    float v;
    if (j < HID) v = Wm[s * HID * HID + k * HID + j];      // h @ W_mpnn[s]
    else         v = whh[(j - HID) * HID + k];             // h @ w_hh^T
    Wcat[idx] = v;
}

__global__ void pack_wihT_kernel(const float* __restrict__ wih,
                                 float* __restrict__ WihT) {
    int idx = blockIdx.x * blockDim.x + threadIdx.x;
    if (idx >= HID * 384) return;
    int k = idx / 384;
    int j = idx % 384;
    WihT[idx] = wih[j * HID + k];
}

// ---------------- SGEMM: C[M,N] = A[M,K] @ B[K,N] (+bias, +act) -------------
#define BM 128
#define BN 128
#define BKK 8
#define TM 8
#define TN 8

__global__ __launch_bounds__(256, 2)
void sgemm_kernel(const float* __restrict__ A, const float* __restrict__ B,
                  float* __restrict__ C, int M, int K, int N,
                  const float* __restrict__ bias, int bias_col0, int act) {
    __shared__ float As[BKK][BM];
    __shared__ float Bs[BKK][BN];

    const int row0 = blockIdx.y * BM;
    const int col0 = blockIdx.x * BN;
    const int tid = threadIdx.x;           // 0..255
    const int tx = tid % 16;                // column group
    const int ty = tid / 16;                // row group

    float acc[TM][TN];
#pragma unroll
    for (int i = 0; i < TM; i++)
#pragma unroll
        for (int j = 0; j < TN; j++) acc[i][j] = 0.0f;

    for (int k0 = 0; k0 < K; k0 += BKK) {
        // load A tile: 128 rows x 8 k, transposed into As[kk][row]
#pragma unroll
        for (int l = 0; l < 4; l++) {
            int idx = tid + l * 256;        // 0..1023
            int r = idx / BKK;
            int kk = idx % BKK;
            int gr = row0 + r, gk = k0 + kk;
            float v = 0.0f;
            if (gr < M && gk < K) v = A[(long long)gr * K + gk];
            As[kk][r] = v;
        }
        // load B tile: 8 k x 128 cols
#pragma unroll
        for (int l = 0; l < 4; l++) {
            int idx = tid + l * 256;
            int kk = idx / BN;
            int c = idx % BN;
            int gk = k0 + kk, gc = col0 + c;
            float v = 0.0f;
            if (gk < K && gc < N) v = B[(long long)gk * N + gc];
            Bs[kk][c] = v;
        }
        __syncthreads();

#pragma unroll
        for (int kk = 0; kk < BKK; kk++) {
            float a[TM], b[TN];
            float4 a0 = *(const float4*)&As[kk][ty * TM];
            float4 a1 = *(const float4*)&As[kk][ty * TM + 4];
            a[0]=a0.x; a[1]=a0.y; a[2]=a0.z; a[3]=a0.w;
            a[4]=a1.x; a[5]=a1.y; a[6]=a1.z; a[7]=a1.w;
            float4 b0 = *(const float4*)&Bs[kk][tx * TN];
            float4 b1 = *(const float4*)&Bs[kk][tx * TN + 4];
            b[0]=b0.x; b[1]=b0.y; b[2]=b0.z; b[3]=b0.w;
            b[4]=b1.x; b[5]=b1.y; b[6]=b1.z; b[7]=b1.w;
#pragma unroll
            for (int i = 0; i < TM; i++)
#pragma unroll
                for (int j = 0; j < TN; j++)
                    acc[i][j] = fmaf(a[i], b[j], acc[i][j]);
        }
        __syncthreads();
    }

#pragma unroll
    for (int i = 0; i < TM; i++) {
        int gr = row0 + ty * TM + i;
        if (gr >= M) continue;
#pragma unroll
        for (int j = 0; j < TN; j++) {
            int gc = col0 + tx * TN + j;
            if (gc >= N) continue;
            float v = acc[i][j];
            if (bias != nullptr && gc >= bias_col0) v += bias[gc - bias_col0];
            if (act == 1) v = tanhf(v);
            C[(long long)gr * N + gc] = v;
        }
    }
}

// ---------------- scatter-add: agg[dst] += m[src] (one warp per edge) -------
// edge_index is int32 (JAX x64 disabled downcasts int64 -> int32).
__global__ void scatter_kernel(const int* __restrict__ ei, long long E,
                               const float* __restrict__ out1,
                               float* __restrict__ agg) {
    long long t = (long long)blockIdx.x * blockDim.x + threadIdx.x;
    long long e = t >> 5;
    int lane = (int)(t & 31);
    if (e >= E) return;
    long long s = (long long)ei[e];
    long long d = (long long)ei[E + e];
    float4 v = *(const float4*)&out1[s * 512 + lane * 4];  // m is cols [0,128)
    float* p = &agg[d * HID + lane * 4];
    atomicAdd(p + 0, v.x);
    atomicAdd(p + 1, v.y);
    atomicAdd(p + 2, v.z);
    atomicAdd(p + 3, v.w);
}

// ---------------- GRU gate fuse ---------------------------------------------
__device__ __forceinline__ float sigmoidf_(float x) {
    return 1.0f / (1.0f + expf(-x));
}

__global__ void gate_kernel(const float* __restrict__ gi,
                            const float* __restrict__ out1,
                            float* __restrict__ h, int Nn) {
    long long idx = (long long)blockIdx.x * blockDim.x + threadIdx.x;
    if (idx >= (long long)Nn * HID) return;
    long long n = idx >> 7;
    int j = (int)(idx & 127);
    const float* gir = gi + n * 384;
    const float* ghr = out1 + n * 512 + HID;   // gh is cols [128,512)
    float r    = sigmoidf_(gir[j]       + ghr[j]);
    float z    = sigmoidf_(gir[j + 128] + ghr[j + 128]);
    float cand = tanhf(gir[j + 256] + r * ghr[j + 256]);
    float ho = h[idx];
    h[idx] = (1.0f - z) * cand + z * ho;
}

// ---------------- pooling + head --------------------------------------------
__global__ void pool_kernel(const float* __restrict__ h,
                            const int* __restrict__ batch,
                            float* __restrict__ sums, float* __restrict__ cnt,
                            int Nn) {
    long long idx = (long long)blockIdx.x * blockDim.x + threadIdx.x;
    if (idx >= (long long)Nn * HID) return;
    long long n = idx >> 7;
    int j = (int)(idx & 127);
    int b = batch[n];
    atomicAdd(&sums[b * HID + j], h[idx]);
    if (j == 0) atomicAdd(&cnt[b], 1.0f);
}

__global__ void final_kernel(const float* __restrict__ sums,
                             const float* __restrict__ cnt,
                             const float* __restrict__ w_pred,
                             const float* __restrict__ b_pred,
                             float* __restrict__ out) {
    int g = blockIdx.x;
    int t = threadIdx.x;   // 128
    float c = fmaxf(cnt[g], 1.0f);
    float v = fmaxf(sums[g * HID + t] / c, 0.0f) * w_pred[t];
#pragma unroll
    for (int o = 16; o > 0; o >>= 1) v += __shfl_down_sync(0xffffffffu, v, o);
    __shared__ float ws[4];
    if ((t & 31) == 0) ws[t >> 5] = v;
    __syncthreads();
    if (t == 0) out[g] = ws[0] + ws[1] + ws[2] + ws[3] + b_pred[0];
}

// ---------------- host launcher ---------------------------------------------
extern "C" void kernel_launch(void* const* d_in, const int* in_sizes, int n_in,
                              void* d_out, int out_size) {
    const float* x       = (const float*)d_in[0];
    const int*   ei      = (const int*)d_in[1];
    const int*   batch   = (const int*)d_in[2];
    const float* W_embed = (const float*)d_in[3];
    const float* W_mpnn  = (const float*)d_in[4];
    const float* w_ih    = (const float*)d_in[5];
    const float* w_hh    = (const float*)d_in[6];
    const float* b_ih    = (const float*)d_in[7];
    const float* b_hh    = (const float*)d_in[8];
    const float* w_pred  = (const float*)d_in[9];
    const float* b_pred  = (const float*)d_in[10];
    float* out = (float*)d_out;

    int Nn = in_sizes[2];
    int F  = in_sizes[0] / Nn;
    long long E = in_sizes[1] / 2;
    int steps = in_sizes[4] / (HID * HID);
    int G = out_size;

    // fetch device-global scratch addresses
    float *p_h, *p_out1, *p_agg, *p_gi, *p_Wcat, *p_WihT, *p_sums, *p_cnt;
    cudaGetSymbolAddress((void**)&p_h,    g_h);
    cudaGetSymbolAddress((void**)&p_out1, g_out1);
    cudaGetSymbolAddress((void**)&p_agg,  g_agg);
    cudaGetSymbolAddress((void**)&p_gi,   g_gi);
    cudaGetSymbolAddress((void**)&p_Wcat, g_Wcat);
    cudaGetSymbolAddress((void**)&p_WihT, g_WihT);
    cudaGetSymbolAddress((void**)&p_sums, g_sums);
    cudaGetSymbolAddress((void**)&p_cnt,  g_cnt);

    // pack weights
    {
        int total = steps * HID * 512;
        pack_wcat_kernel<<<(total + 255) / 256, 256>>>(W_mpnn, w_hh, p_Wcat, steps);
        pack_wihT_kernel<<<(HID * 384 + 255) / 256, 256>>>(w_ih, p_WihT);
    }

    int mt = (Nn + BM - 1) / BM;

    // embed: h = tanh(x @ W_embed)   [N,F] x [F,128]
    sgemm_kernel<<<dim3(1, mt), 256>>>(x, W_embed, p_h, Nn, F, HID,
                                       nullptr, 0, 1);

    long long nh = (long long)Nn * HID;
    int zb = (int)((nh + 255) / 256);
    if (zb > 65535) zb = 65535;

    for (int s = 0; s < steps; s++) {
        // [m | gh] = h @ [W_mpnn[s] | w_hh^T]  (+b_hh on gh part)
        sgemm_kernel<<<dim3(512 / BN, mt), 256>>>(
            p_h, p_Wcat + (long long)s * HID * 512, p_out1,
            Nn, HID, 512, b_hh, HID, 0);

        zero_kernel<<<zb, 256>>>(p_agg, nh);

        long long nthr = E * 32;
        int sb = (int)((nthr + 255) / 256);
        scatter_kernel<<<sb, 256>>>(ei, E, p_out1, p_agg);

        // gi = agg @ w_ih^T + b_ih
        sgemm_kernel<<<dim3(384 / BN, mt), 256>>>(
            p_agg, p_WihT, p_gi, Nn, HID, 384, b_ih, 0, 0);

        gate_kernel<<<(int)((nh + 255) / 256), 256>>>(p_gi, p_out1, p_h, Nn);
    }

    // pooling
    zero_kernel<<<(NG * HID + 255) / 256, 256>>>(p_sums, NG * HID);
    zero_kernel<<<1, 256>>>(p_cnt, NG);
    pool_kernel<<<(int)((nh + 255) / 256), 256>>>(p_h, batch, p_sums, p_cnt, Nn);
    final_kernel<<<G, HID>>>(p_sums, p_cnt, w_pred, b_pred, out);
}

// round 4
// speedup vs baseline: 1.5757x; 1.5757x over previous
#include <cuda_runtime.h>
#include <cuda_bf16.h>
#include <math.h>
#include <stdint.h>

#define HID 128
#define MAX_N 100352
#define MAXSTEPS 8
#define NG 256

// ---------------- scratch (static device globals; no runtime allocation) ----
__device__ __align__(16) float g_h   [MAX_N * HID];
__device__ __align__(16) float g_out1[MAX_N * 512];
__device__ __align__(16) float g_agg [MAX_N * HID];
__device__ __align__(16) float g_gi  [MAX_N * 384];
__device__ __align__(16) float g_Wcat[MAXSTEPS * HID * 512];
__device__ __align__(16) float g_WihT[HID * 384];
__device__ __align__(16) float g_sums[NG * HID];
__device__ __align__(16) float g_cnt [NG];

// ---------------- utility kernels ------------------------------------------
__global__ void zero_kernel(float* p, long long n) {
    long long i = (long long)blockIdx.x * blockDim.x + threadIdx.x;
    long long stride = (long long)gridDim.x * blockDim.x;
    for (; i < n; i += stride) p[i] = 0.0f;
}

__global__ void pack_wcat_kernel(const float* __restrict__ Wm,
                                 const float* __restrict__ whh,
                                 float* __restrict__ Wcat, int steps) {
    int idx = blockIdx.x * blockDim.x + threadIdx.x;
    int total = steps * HID * 512;
    if (idx >= total) return;
    int s = idx / (HID * 512);
    int rem = idx % (HID * 512);
    int k = rem / 512;
    int j = rem % 512;
    float v;
    if (j < HID) v = Wm[s * HID * HID + k * HID + j];
    else         v = whh[(j - HID) * HID + k];
    Wcat[idx] = v;
}

__global__ void pack_wihT_kernel(const float* __restrict__ wih,
                                 float* __restrict__ WihT) {
    int idx = blockIdx.x * blockDim.x + threadIdx.x;
    if (idx >= HID * 384) return;
    int k = idx / 384;
    int j = idx % 384;
    WihT[idx] = wih[j * HID + k];
}

// ---------------- bf16-split tensor-core GEMM -------------------------------
// C[M,N] = A[M,K] @ B[K,N] (+bias over cols>=bias_col0, act=1 -> tanh)
// fp32 emulated as hi+lo bf16 split; D = Ah*Bh + Ah*Bl + Al*Bh (fp32 accum).
// 128x128 CTA tile, BK=32, 256 threads = 8 warps (2x4), warp tile 64x32.

__device__ __forceinline__ void mma_bf16(float* c, const uint32_t* a, const uint32_t* b) {
    asm volatile(
        "mma.sync.aligned.m16n8k16.row.col.f32.bf16.bf16.f32 "
        "{%0,%1,%2,%3}, {%4,%5,%6,%7}, {%8,%9}, {%0,%1,%2,%3};\n"
        : "+f"(c[0]), "+f"(c[1]), "+f"(c[2]), "+f"(c[3])
        : "r"(a[0]), "r"(a[1]), "r"(a[2]), "r"(a[3]),
          "r"(b[0]), "r"(b[1]));
}

// split two floats (k, k+1) into bf16x2 hi / lo words (low 16 bits = first k)
__device__ __forceinline__ void split2(float x, float y, uint32_t& hi, uint32_t& lo) {
    __nv_bfloat16 hx = __float2bfloat16_rn(x);
    __nv_bfloat16 hy = __float2bfloat16_rn(y);
    float rx = x - __bfloat162float(hx);
    float ry = y - __bfloat162float(hy);
    __nv_bfloat162 h; h.x = hx; h.y = hy;
    __nv_bfloat162 l; l.x = __float2bfloat16_rn(rx); l.y = __float2bfloat16_rn(ry);
    hi = *(uint32_t*)&h;
    lo = *(uint32_t*)&l;
}

#define PA 20    // AsH/AsL pitch in uint32 pairs (16 used) -> conflict-free frag LDS
#define PB 136   // BsH/BsL pitch in uint32 cols (128 used) -> conflict-free frag LDS

__global__ __launch_bounds__(256)
void mma_gemm_kernel(const float* __restrict__ A, const float* __restrict__ B,
                     float* __restrict__ C, int M, int K, int N,
                     const float* __restrict__ bias, int bias_col0, int act) {
    // A pairs: [row][kpair]; B pairs: [kpair][col]
    __shared__ uint32_t AsH[128][PA];
    __shared__ uint32_t AsL[128][PA];
    __shared__ uint32_t BsH[16][PB];
    __shared__ uint32_t BsL[16][PB];

    const int tid  = threadIdx.x;
    const int lane = tid & 31;
    const int warp = tid >> 5;
    const int warpM = warp >> 2;   // 0..1
    const int warpN = warp & 3;    // 0..3
    const int row0 = blockIdx.y * 128;
    const int col0 = blockIdx.x * 128;

    float acc[4][4][4];
#pragma unroll
    for (int mi = 0; mi < 4; mi++)
#pragma unroll
        for (int ni = 0; ni < 4; ni++)
#pragma unroll
            for (int q = 0; q < 4; q++) acc[mi][ni][q] = 0.0f;

    for (int kt = 0; kt < K; kt += 32) {
        // ---- load + split A tile: 128 rows x 32 k -> pairs [128][16] ----
#pragma unroll
        for (int i = 0; i < 4; i++) {
            int r   = (tid >> 3) + i * 32;     // 0..127
            int kp0 = (tid & 7) * 2;           // pair index, step 2
            int gr  = row0 + r;
            int gk  = kt + kp0 * 2;            // element k
            float4 v = make_float4(0.f, 0.f, 0.f, 0.f);
            if (gr < M) {
                if (gk + 3 < K) {
                    v = *(const float4*)(A + (long long)gr * K + gk);
                } else {
                    float* pv = (float*)&v;
#pragma unroll
                    for (int d = 0; d < 4; d++)
                        if (gk + d < K) pv[d] = A[(long long)gr * K + gk + d];
                }
            }
            uint32_t h0, l0, h1, l1;
            split2(v.x, v.y, h0, l0);
            split2(v.z, v.w, h1, l1);
            AsH[r][kp0] = h0; AsH[r][kp0 + 1] = h1;
            AsL[r][kp0] = l0; AsL[r][kp0 + 1] = l1;
        }
        // ---- load + split B tile: 32 k x 128 cols -> pairs [16][128] ----
#pragma unroll
        for (int i = 0; i < 2; i++) {
            int kp = (tid >> 5) + i * 8;       // 0..15
            int c4 = (tid & 31) * 4;
            int gk = kt + kp * 2;
            float4 v0 = make_float4(0.f, 0.f, 0.f, 0.f);
            float4 v1 = make_float4(0.f, 0.f, 0.f, 0.f);
            if (gk < K)     v0 = *(const float4*)(B + (long long)gk * N + col0 + c4);
            if (gk + 1 < K) v1 = *(const float4*)(B + (long long)(gk + 1) * N + col0 + c4);
            uint4 uh, ul;
            split2(v0.x, v1.x, uh.x, ul.x);
            split2(v0.y, v1.y, uh.y, ul.y);
            split2(v0.z, v1.z, uh.z, ul.z);
            split2(v0.w, v1.w, uh.w, ul.w);
            *(uint4*)&BsH[kp][c4] = uh;
            *(uint4*)&BsL[kp][c4] = ul;
        }
        __syncthreads();

        // ---- 2 chunks of k16 per tile ----
#pragma unroll
        for (int ks = 0; ks < 2; ks++) {
            const int kp0 = ks * 8;
            uint32_t afh[4][4], afl[4][4];
#pragma unroll
            for (int mi = 0; mi < 4; mi++) {
                int rb = warpM * 64 + mi * 16 + (lane >> 2);
                int kc = kp0 + (lane & 3);
                afh[mi][0] = AsH[rb][kc];
                afh[mi][1] = AsH[rb + 8][kc];
                afh[mi][2] = AsH[rb][kc + 4];
                afh[mi][3] = AsH[rb + 8][kc + 4];
                afl[mi][0] = AsL[rb][kc];
                afl[mi][1] = AsL[rb + 8][kc];
                afl[mi][2] = AsL[rb][kc + 4];
                afl[mi][3] = AsL[rb + 8][kc + 4];
            }
            uint32_t bfh[4][2], bfl[4][2];
#pragma unroll
            for (int ni = 0; ni < 4; ni++) {
                int cb = warpN * 32 + ni * 8 + (lane >> 2);
                bfh[ni][0] = BsH[kp0 + (lane & 3)][cb];
                bfh[ni][1] = BsH[kp0 + 4 + (lane & 3)][cb];
                bfl[ni][0] = BsL[kp0 + (lane & 3)][cb];
                bfl[ni][1] = BsL[kp0 + 4 + (lane & 3)][cb];
            }
#pragma unroll
            for (int mi = 0; mi < 4; mi++)
#pragma unroll
                for (int ni = 0; ni < 4; ni++) {
                    mma_bf16(acc[mi][ni], afh[mi], bfl[ni]);
                    mma_bf16(acc[mi][ni], afl[mi], bfh[ni]);
                    mma_bf16(acc[mi][ni], afh[mi], bfh[ni]);
                }
        }
        __syncthreads();
    }

    // ---- epilogue ----
#pragma unroll
    for (int mi = 0; mi < 4; mi++) {
#pragma unroll
        for (int ni = 0; ni < 4; ni++) {
            int c = col0 + warpN * 32 + ni * 8 + (lane & 3) * 2;
#pragma unroll
            for (int half = 0; half < 2; half++) {
                int r = row0 + warpM * 64 + mi * 16 + (lane >> 2) + half * 8;
                if (r >= M) continue;
                float v0 = acc[mi][ni][half * 2 + 0];
                float v1 = acc[mi][ni][half * 2 + 1];
                if (bias != nullptr && c >= bias_col0) {
                    v0 += bias[c - bias_col0];
                    v1 += bias[c + 1 - bias_col0];
                }
                if (act == 1) { v0 = tanhf(v0); v1 = tanhf(v1); }
                *(float2*)(C + (long long)r * N + c) = make_float2(v0, v1);
            }
        }
    }
}

// ---------------- scatter-add: agg[dst] += m[src] (one warp per edge) -------
__global__ void scatter_kernel(const int* __restrict__ ei, long long E,
                               const float* __restrict__ out1,
                               float* __restrict__ agg) {
    long long t = (long long)blockIdx.x * blockDim.x + threadIdx.x;
    long long e = t >> 5;
    int lane = (int)(t & 31);
    if (e >= E) return;
    long long s = (long long)ei[e];
    long long d = (long long)ei[E + e];
    float4 v = *(const float4*)&out1[s * 512 + lane * 4];
    float* p = &agg[d * HID + lane * 4];
    atomicAdd(p + 0, v.x);
    atomicAdd(p + 1, v.y);
    atomicAdd(p + 2, v.z);
    atomicAdd(p + 3, v.w);
}

// ---------------- GRU gate fuse (float4) ------------------------------------
__device__ __forceinline__ float sigmoidf_(float x) {
    return 1.0f / (1.0f + expf(-x));
}

__global__ void gate_kernel(const float* __restrict__ gi,
                            const float* __restrict__ out1,
                            float* __restrict__ h, int Nn) {
    long long idx = (long long)blockIdx.x * blockDim.x + threadIdx.x;
    if (idx >= (long long)Nn * 32) return;
    long long n = idx >> 5;
    int j = (int)(idx & 31) * 4;
    const float* gir = gi + n * 384;
    const float* ghr = out1 + n * 512 + HID;
    float4 ir = *(const float4*)&gir[j];
    float4 iz = *(const float4*)&gir[j + 128];
    float4 in_ = *(const float4*)&gir[j + 256];
    float4 hr = *(const float4*)&ghr[j];
    float4 hz = *(const float4*)&ghr[j + 128];
    float4 hn = *(const float4*)&ghr[j + 256];
    float4 ho = *(const float4*)&h[n * HID + j];
    float4 res;
    {
        float r = sigmoidf_(ir.x + hr.x);
        float z = sigmoidf_(iz.x + hz.x);
        float cand = tanhf(in_.x + r * hn.x);
        res.x = (1.0f - z) * cand + z * ho.x;
    }
    {
        float r = sigmoidf_(ir.y + hr.y);
        float z = sigmoidf_(iz.y + hz.y);
        float cand = tanhf(in_.y + r * hn.y);
        res.y = (1.0f - z) * cand + z * ho.y;
    }
    {
        float r = sigmoidf_(ir.z + hr.z);
        float z = sigmoidf_(iz.z + hz.z);
        float cand = tanhf(in_.z + r * hn.z);
        res.z = (1.0f - z) * cand + z * ho.z;
    }
    {
        float r = sigmoidf_(ir.w + hr.w);
        float z = sigmoidf_(iz.w + hz.w);
        float cand = tanhf(in_.w + r * hn.w);
        res.w = (1.0f - z) * cand + z * ho.w;
    }
    *(float4*)&h[n * HID + j] = res;
}

// ---------------- pooling + head --------------------------------------------
__global__ void pool_kernel(const float* __restrict__ h,
                            const int* __restrict__ batch,
                            float* __restrict__ sums, float* __restrict__ cnt,
                            int Nn) {
    long long idx = (long long)blockIdx.x * blockDim.x + threadIdx.x;
    if (idx >= (long long)Nn * HID) return;
    long long n = idx >> 7;
    int j = (int)(idx & 127);
    int b = batch[n];
    atomicAdd(&sums[b * HID + j], h[idx]);
    if (j == 0) atomicAdd(&cnt[b], 1.0f);
}

__global__ void final_kernel(const float* __restrict__ sums,
                             const float* __restrict__ cnt,
                             const float* __restrict__ w_pred,
                             const float* __restrict__ b_pred,
                             float* __restrict__ out) {
    int g = blockIdx.x;
    int t = threadIdx.x;   // 128
    float c = fmaxf(cnt[g], 1.0f);
    float v = fmaxf(sums[g * HID + t] / c, 0.0f) * w_pred[t];
#pragma unroll
    for (int o = 16; o > 0; o >>= 1) v += __shfl_down_sync(0xffffffffu, v, o);
    __shared__ float ws[4];
    if ((t & 31) == 0) ws[t >> 5] = v;
    __syncthreads();
    if (t == 0) out[g] = ws[0] + ws[1] + ws[2] + ws[3] + b_pred[0];
}

// ---------------- host launcher ---------------------------------------------
extern "C" void kernel_launch(void* const* d_in, const int* in_sizes, int n_in,
                              void* d_out, int out_size) {
    const float* x       = (const float*)d_in[0];
    const int*   ei      = (const int*)d_in[1];
    const int*   batch   = (const int*)d_in[2];
    const float* W_embed = (const float*)d_in[3];
    const float* W_mpnn  = (const float*)d_in[4];
    const float* w_ih    = (const float*)d_in[5];
    const float* w_hh    = (const float*)d_in[6];
    const float* b_ih    = (const float*)d_in[7];
    const float* b_hh    = (const float*)d_in[8];
    const float* w_pred  = (const float*)d_in[9];
    const float* b_pred  = (const float*)d_in[10];
    float* out = (float*)d_out;

    int Nn = in_sizes[2];
    long long E = in_sizes[1] / 2;
    int steps = in_sizes[4] / (HID * HID);
    int F  = in_sizes[0] / Nn;
    int G = out_size;

    float *p_h, *p_out1, *p_agg, *p_gi, *p_Wcat, *p_WihT, *p_sums, *p_cnt;
    cudaGetSymbolAddress((void**)&p_h,    g_h);
    cudaGetSymbolAddress((void**)&p_out1, g_out1);
    cudaGetSymbolAddress((void**)&p_agg,  g_agg);
    cudaGetSymbolAddress((void**)&p_gi,   g_gi);
    cudaGetSymbolAddress((void**)&p_Wcat, g_Wcat);
    cudaGetSymbolAddress((void**)&p_WihT, g_WihT);
    cudaGetSymbolAddress((void**)&p_sums, g_sums);
    cudaGetSymbolAddress((void**)&p_cnt,  g_cnt);

    {
        int total = steps * HID * 512;
        pack_wcat_kernel<<<(total + 255) / 256, 256>>>(W_mpnn, w_hh, p_Wcat, steps);
        pack_wihT_kernel<<<(HID * 384 + 255) / 256, 256>>>(w_ih, p_WihT);
    }

    int mt = (Nn + 127) / 128;

    // embed: h = tanh(x @ W_embed)   [N,F] x [F,128]
    mma_gemm_kernel<<<dim3(1, mt), 256>>>(x, W_embed, p_h, Nn, F, HID,
                                          nullptr, 0, 1);

    long long nh = (long long)Nn * HID;
    int zb = (int)((nh + 255) / 256);
    if (zb > 65535) zb = 65535;

    for (int s = 0; s < steps; s++) {
        // [m | gh] = h @ [W_mpnn[s] | w_hh^T]  (+b_hh on gh cols)
        mma_gemm_kernel<<<dim3(4, mt), 256>>>(
            p_h, p_Wcat + (long long)s * HID * 512, p_out1,
            Nn, HID, 512, b_hh, HID, 0);

        zero_kernel<<<zb, 256>>>(p_agg, nh);

        long long nthr = E * 32;
        int sb = (int)((nthr + 255) / 256);
        scatter_kernel<<<sb, 256>>>(ei, E, p_out1, p_agg);

        // gi = agg @ w_ih^T + b_ih
        mma_gemm_kernel<<<dim3(3, mt), 256>>>(
            p_agg, p_WihT, p_gi, Nn, HID, 384, b_ih, 0, 0);

        gate_kernel<<<(int)((nh / 4 + 255) / 256), 256>>>(p_gi, p_out1, p_h, Nn);
    }

    zero_kernel<<<(NG * HID + 255) / 256, 256>>>(p_sums, NG * HID);
    zero_kernel<<<1, 256>>>(p_cnt, NG);
    pool_kernel<<<(int)((nh + 255) / 256), 256>>>(p_h, batch, p_sums, p_cnt, Nn);
    final_kernel<<<G, HID>>>(p_sums, p_cnt, w_pred, b_pred, out);
}

// round 5
// speedup vs baseline: 3.2399x; 2.0562x over previous
#include <cuda_runtime.h>
#include <cuda_bf16.h>
#include <math.h>
#include <stdint.h>

#define HID 128
#define MAX_N 100352
#define MAXSTEPS 8
#define NG 256
#define MAX_E 2000000

// ---------------- scratch (static device globals; no runtime allocation) ----
__device__ __align__(16) float    g_h   [MAX_N * HID];
__device__ __align__(16) float    g_out1[MAX_N * 512];
__device__ __align__(16) float    g_gi  [MAX_N * 384];
__device__ __align__(16) uint32_t g_hH  [MAX_N * 64];
__device__ __align__(16) uint32_t g_hL  [MAX_N * 64];
__device__ __align__(16) uint32_t g_aggH[MAX_N * 64];
__device__ __align__(16) uint32_t g_aggL[MAX_N * 64];
__device__ __align__(16) uint32_t g_xH  [MAX_N * 48];
__device__ __align__(16) uint32_t g_xL  [MAX_N * 48];
__device__ __align__(16) uint32_t g_WcatH[MAXSTEPS * 64 * 512];
__device__ __align__(16) uint32_t g_WcatL[MAXSTEPS * 64 * 512];
__device__ __align__(16) uint32_t g_WihTH[64 * 384];
__device__ __align__(16) uint32_t g_WihTL[64 * 384];
__device__ __align__(16) uint32_t g_WembH[48 * 128];
__device__ __align__(16) uint32_t g_WembL[48 * 128];
__device__ int g_deg[MAX_N];
__device__ int g_rowptr[MAX_N + 1];
__device__ int g_cursor[MAX_N];
__device__ int g_esrc[MAX_E];
__device__ __align__(16) float g_sums[NG * HID];
__device__ __align__(16) float g_cnt [NG];

// ---------------- helpers ----------------------------------------------------
__device__ __forceinline__ void split2(float x, float y, uint32_t& hi, uint32_t& lo) {
    __nv_bfloat16 hx = __float2bfloat16_rn(x);
    __nv_bfloat16 hy = __float2bfloat16_rn(y);
    float rx = x - __bfloat162float(hx);
    float ry = y - __bfloat162float(hy);
    __nv_bfloat162 h; h.x = hx; h.y = hy;
    __nv_bfloat162 l; l.x = __float2bfloat16_rn(rx); l.y = __float2bfloat16_rn(ry);
    hi = *(uint32_t*)&h;
    lo = *(uint32_t*)&l;
}

__device__ __forceinline__ void mma_bf16(float* c, const uint32_t* a, const uint32_t* b) {
    asm volatile(
        "mma.sync.aligned.m16n8k16.row.col.f32.bf16.bf16.f32 "
        "{%0,%1,%2,%3}, {%4,%5,%6,%7}, {%8,%9}, {%0,%1,%2,%3};\n"
        : "+f"(c[0]), "+f"(c[1]), "+f"(c[2]), "+f"(c[3])
        : "r"(a[0]), "r"(a[1]), "r"(a[2]), "r"(a[3]),
          "r"(b[0]), "r"(b[1]));
}

__device__ __forceinline__ float sigmoidf_(float x) {
    return 1.0f / (1.0f + expf(-x));
}

// ---------------- small utility kernels --------------------------------------
__global__ void zero_f(float* p, long long n) {
    long long i = (long long)blockIdx.x * blockDim.x + threadIdx.x;
    if (i < n) p[i] = 0.0f;
}
__global__ void zero_i(int* p, int n) {
    int i = blockIdx.x * blockDim.x + threadIdx.x;
    if (i < n) p[i] = 0;
}

// ---------------- weight / input pre-split kernels ---------------------------
// WcatH/L: [steps][64 kpairs][512 cols]; cols 0..127 = W_mpnn[s], 128..511 = w_hh^T
__global__ void pack_wcat_kernel(const float* __restrict__ Wm,
                                 const float* __restrict__ whh,
                                 uint32_t* __restrict__ WH, uint32_t* __restrict__ WL,
                                 int steps) {
    int idx = blockIdx.x * blockDim.x + threadIdx.x;
    int total = steps * 64 * 512;
    if (idx >= total) return;
    int s = idx / (64 * 512);
    int rem = idx % (64 * 512);
    int p = rem / 512;
    int j = rem % 512;
    float a, b;
    if (j < HID) {
        a = Wm[s * HID * HID + (2 * p) * HID + j];
        b = Wm[s * HID * HID + (2 * p + 1) * HID + j];
    } else {
        int jj = j - HID;
        a = whh[jj * HID + 2 * p];
        b = whh[jj * HID + 2 * p + 1];
    }
    uint32_t h, l;
    split2(a, b, h, l);
    WH[idx] = h; WL[idx] = l;
}

// WihTH/L: [64 kpairs][384 cols]
__global__ void pack_wihT_kernel(const float* __restrict__ wih,
                                 uint32_t* __restrict__ WH, uint32_t* __restrict__ WL) {
    int idx = blockIdx.x * blockDim.x + threadIdx.x;
    if (idx >= 64 * 384) return;
    int p = idx / 384;
    int j = idx % 384;
    uint32_t h, l;
    split2(wih[j * HID + 2 * p], wih[j * HID + 2 * p + 1], h, l);
    WH[idx] = h; WL[idx] = l;
}

// WembH/L: [48 kpair rows (padded)][128 cols]
__global__ void pack_wemb_kernel(const float* __restrict__ We,
                                 uint32_t* __restrict__ WH, uint32_t* __restrict__ WL,
                                 int KPx) {
    int idx = blockIdx.x * blockDim.x + threadIdx.x;
    if (idx >= 48 * 128) return;
    int p = idx / 128;
    int j = idx % 128;
    uint32_t h = 0, l = 0;
    if (p < KPx) split2(We[(2 * p) * HID + j], We[(2 * p + 1) * HID + j], h, l);
    WH[idx] = h; WL[idx] = l;
}

// xH/L: [N][48 kpairs padded]
__global__ void split_x_kernel(const float* __restrict__ x,
                               uint32_t* __restrict__ xH, uint32_t* __restrict__ xL,
                               int Nn, int F, int KPx, int Apx) {
    long long idx = (long long)blockIdx.x * blockDim.x + threadIdx.x;
    if (idx >= (long long)Nn * Apx) return;
    int n = (int)(idx / Apx);
    int p = (int)(idx % Apx);
    uint32_t h = 0, l = 0;
    if (p < KPx) split2(x[(long long)n * F + 2 * p], x[(long long)n * F + 2 * p + 1], h, l);
    xH[idx] = h; xL[idx] = l;
}

// ---------------- CSR build ---------------------------------------------------
__global__ void hist_kernel(const int* __restrict__ ei, long long E, int* __restrict__ deg) {
    long long e = (long long)blockIdx.x * blockDim.x + threadIdx.x;
    if (e >= E) return;
    atomicAdd(&deg[ei[E + e]], 1);
}

// single-block exclusive scan (1024 threads), writes rowptr[N+1] and cursor[N]
__global__ void scan_kernel(const int* __restrict__ deg, int* __restrict__ rowptr,
                            int* __restrict__ cursor, int Nn) {
    __shared__ int warpsums[32];
    const int tid = threadIdx.x;
    const int lane = tid & 31;
    const int wid = tid >> 5;
    int carry = 0;
    for (int base = 0; base < Nn; base += 1024) {
        int idx = base + tid;
        int v = (idx < Nn) ? deg[idx] : 0;
        int x = v;
#pragma unroll
        for (int off = 1; off < 32; off <<= 1) {
            int y = __shfl_up_sync(0xffffffffu, x, off);
            if (lane >= off) x += y;
        }
        if (lane == 31) warpsums[wid] = x;
        __syncthreads();
        if (wid == 0) {
            int z = warpsums[lane];
#pragma unroll
            for (int off = 1; off < 32; off <<= 1) {
                int y = __shfl_up_sync(0xffffffffu, z, off);
                if (lane >= off) z += y;
            }
            warpsums[lane] = z;
        }
        __syncthreads();
        int pref = (wid > 0) ? warpsums[wid - 1] : 0;
        int excl = carry + pref + x - v;
        if (idx < Nn) { rowptr[idx] = excl; cursor[idx] = excl; }
        carry += warpsums[31];
        __syncthreads();
    }
    if (tid == 0) rowptr[Nn] = carry;
}

__global__ void fill_kernel(const int* __restrict__ ei, long long E,
                            int* __restrict__ cursor, int* __restrict__ esrc) {
    long long e = (long long)blockIdx.x * blockDim.x + threadIdx.x;
    if (e >= E) return;
    int s = ei[e];
    int d = ei[E + e];
    int p = atomicAdd(&cursor[d], 1);
    esrc[p] = s;
}

// ---------------- bf16-split tensor-core GEMM --------------------------------
// C[M,N] = A[M,K] @ B[K,N]; A given pre-split as AH/AL [M][Apitch kpairs],
// B pre-split as BH/BL [kpair][N]. D = Ah*Bh + Ah*Bl + Al*Bh (fp32 accum).
// 128x128 CTA tile, 16 kpairs (32 k) per smem tile, 256 thr = 8 warps (2x4).

__global__ __launch_bounds__(256)
void mma_gemm_kernel(const uint32_t* __restrict__ AH, const uint32_t* __restrict__ AL,
                     int KP, int Apitch,
                     const uint32_t* __restrict__ BH, const uint32_t* __restrict__ BL,
                     float* __restrict__ C, int M, int N,
                     const float* __restrict__ bias, int bias_col0, int act,
                     uint32_t* __restrict__ outH, uint32_t* __restrict__ outL, int opitch) {
    __shared__ uint32_t AsH[128][20];
    __shared__ uint32_t AsL[128][20];
    __shared__ uint32_t BsH[16][136];
    __shared__ uint32_t BsL[16][136];

    const int tid  = threadIdx.x;
    const int lane = tid & 31;
    const int warp = tid >> 5;
    const int warpM = warp >> 2;   // 0..1
    const int warpN = warp & 3;    // 0..3
    const int row0 = blockIdx.y * 128;
    const int col0 = blockIdx.x * 128;

    float acc[4][4][4];
#pragma unroll
    for (int mi = 0; mi < 4; mi++)
#pragma unroll
        for (int ni = 0; ni < 4; ni++)
#pragma unroll
            for (int q = 0; q < 4; q++) acc[mi][ni][q] = 0.0f;

    const int ntiles = (KP + 15) >> 4;
    for (int t = 0; t < ntiles; t++) {
        const int ktp = t * 16;
        // ---- A tile: 128 rows x 16 kpairs ----
#pragma unroll
        for (int i = 0; i < 2; i++) {
            int r   = (tid >> 2) + i * 64;
            int kp4 = (tid & 3) * 4;
            int gr  = row0 + r;
            uint4 vh = make_uint4(0, 0, 0, 0);
            uint4 vl = make_uint4(0, 0, 0, 0);
            if (gr < M) {
                long long off = (long long)gr * Apitch + ktp + kp4;
                vh = *(const uint4*)&AH[off];
                vl = *(const uint4*)&AL[off];
            }
            *(uint4*)&AsH[r][kp4] = vh;
            *(uint4*)&AsL[r][kp4] = vl;
        }
        // ---- B tile: 16 kpairs x 128 cols ----
#pragma unroll
        for (int i = 0; i < 2; i++) {
            int kp = (tid >> 5) + i * 8;
            int c4 = (tid & 31) * 4;
            long long off = (long long)(ktp + kp) * N + col0 + c4;
            uint4 vh = *(const uint4*)&BH[off];
            uint4 vl = *(const uint4*)&BL[off];
            *(uint4*)&BsH[kp][c4] = vh;
            *(uint4*)&BsL[kp][c4] = vl;
        }
        __syncthreads();

#pragma unroll
        for (int ks = 0; ks < 2; ks++) {
            const int kp0 = ks * 8;
            uint32_t afh[4][4], afl[4][4];
#pragma unroll
            for (int mi = 0; mi < 4; mi++) {
                int rb = warpM * 64 + mi * 16 + (lane >> 2);
                int kc = kp0 + (lane & 3);
                afh[mi][0] = AsH[rb][kc];
                afh[mi][1] = AsH[rb + 8][kc];
                afh[mi][2] = AsH[rb][kc + 4];
                afh[mi][3] = AsH[rb + 8][kc + 4];
                afl[mi][0] = AsL[rb][kc];
                afl[mi][1] = AsL[rb + 8][kc];
                afl[mi][2] = AsL[rb][kc + 4];
                afl[mi][3] = AsL[rb + 8][kc + 4];
            }
            uint32_t bfh[4][2], bfl[4][2];
#pragma unroll
            for (int ni = 0; ni < 4; ni++) {
                int cb = warpN * 32 + ni * 8 + (lane >> 2);
                bfh[ni][0] = BsH[kp0 + (lane & 3)][cb];
                bfh[ni][1] = BsH[kp0 + 4 + (lane & 3)][cb];
                bfl[ni][0] = BsL[kp0 + (lane & 3)][cb];
                bfl[ni][1] = BsL[kp0 + 4 + (lane & 3)][cb];
            }
#pragma unroll
            for (int mi = 0; mi < 4; mi++)
#pragma unroll
                for (int ni = 0; ni < 4; ni++) {
                    mma_bf16(acc[mi][ni], afh[mi], bfl[ni]);
                    mma_bf16(acc[mi][ni], afl[mi], bfh[ni]);
                    mma_bf16(acc[mi][ni], afh[mi], bfh[ni]);
                }
        }
        __syncthreads();
    }

    // ---- epilogue ----
#pragma unroll
    for (int mi = 0; mi < 4; mi++) {
#pragma unroll
        for (int ni = 0; ni < 4; ni++) {
            int c = col0 + warpN * 32 + ni * 8 + (lane & 3) * 2;
#pragma unroll
            for (int half = 0; half < 2; half++) {
                int r = row0 + warpM * 64 + mi * 16 + (lane >> 2) + half * 8;
                if (r >= M) continue;
                float v0 = acc[mi][ni][half * 2 + 0];
                float v1 = acc[mi][ni][half * 2 + 1];
                if (bias != nullptr && c >= bias_col0) {
                    v0 += bias[c - bias_col0];
                    v1 += bias[c + 1 - bias_col0];
                }
                if (act == 1) { v0 = tanhf(v0); v1 = tanhf(v1); }
                *(float2*)(C + (long long)r * N + c) = make_float2(v0, v1);
                if (outH != nullptr) {
                    uint32_t hh, ll;
                    split2(v0, v1, hh, ll);
                    outH[(long long)r * opitch + (c >> 1)] = hh;
                    outL[(long long)r * opitch + (c >> 1)] = ll;
                }
            }
        }
    }
}

// ---------------- CSR gather-reduce: agg[n] = sum_{e: dst=n} m[src_e] --------
// one warp per node; writes bf16-split agg directly
__global__ void gather_kernel(const int* __restrict__ rowptr,
                              const int* __restrict__ esrc,
                              const float* __restrict__ out1,
                              uint32_t* __restrict__ aggH, uint32_t* __restrict__ aggL,
                              int Nn) {
    int w = (int)(((long long)blockIdx.x * blockDim.x + threadIdx.x) >> 5);
    int lane = threadIdx.x & 31;
    if (w >= Nn) return;
    int i = rowptr[w];
    const int end = rowptr[w + 1];
    float4 acc = make_float4(0.f, 0.f, 0.f, 0.f);
    int s0 = (i < end) ? esrc[i] : 0;
    int s1 = (i + 1 < end) ? esrc[i + 1] : 0;
    while (i < end) {
        int s = s0;
        s0 = s1;
        s1 = (i + 2 < end) ? esrc[i + 2] : 0;
        float4 v = *(const float4*)&out1[(long long)s * 512 + lane * 4];
        acc.x += v.x; acc.y += v.y; acc.z += v.z; acc.w += v.w;
        i++;
    }
    uint32_t h0, l0, h1, l1;
    split2(acc.x, acc.y, h0, l0);
    split2(acc.z, acc.w, h1, l1);
    long long b = (long long)w * 64 + lane * 2;
    aggH[b] = h0; aggH[b + 1] = h1;
    aggL[b] = l0; aggL[b + 1] = l1;
}

// ---------------- GRU gate fuse (float4) + h split ---------------------------
__global__ void gate_kernel(const float* __restrict__ gi,
                            const float* __restrict__ out1,
                            float* __restrict__ h,
                            uint32_t* __restrict__ hH, uint32_t* __restrict__ hL,
                            int Nn) {
    long long idx = (long long)blockIdx.x * blockDim.x + threadIdx.x;
    if (idx >= (long long)Nn * 32) return;
    long long n = idx >> 5;
    int j = (int)(idx & 31) * 4;
    const float* gir = gi + n * 384;
    const float* ghr = out1 + n * 512 + HID;
    float4 ir = *(const float4*)&gir[j];
    float4 iz = *(const float4*)&gir[j + 128];
    float4 in_ = *(const float4*)&gir[j + 256];
    float4 hr = *(const float4*)&ghr[j];
    float4 hz = *(const float4*)&ghr[j + 128];
    float4 hn = *(const float4*)&ghr[j + 256];
    float4 ho = *(const float4*)&h[n * HID + j];
    float4 res;
    {
        float r = sigmoidf_(ir.x + hr.x);
        float z = sigmoidf_(iz.x + hz.x);
        float cand = tanhf(in_.x + r * hn.x);
        res.x = (1.0f - z) * cand + z * ho.x;
    }
    {
        float r = sigmoidf_(ir.y + hr.y);
        float z = sigmoidf_(iz.y + hz.y);
        float cand = tanhf(in_.y + r * hn.y);
        res.y = (1.0f - z) * cand + z * ho.y;
    }
    {
        float r = sigmoidf_(ir.z + hr.z);
        float z = sigmoidf_(iz.z + hz.z);
        float cand = tanhf(in_.z + r * hn.z);
        res.z = (1.0f - z) * cand + z * ho.z;
    }
    {
        float r = sigmoidf_(ir.w + hr.w);
        float z = sigmoidf_(iz.w + hz.w);
        float cand = tanhf(in_.w + r * hn.w);
        res.w = (1.0f - z) * cand + z * ho.w;
    }
    *(float4*)&h[n * HID + j] = res;
    uint32_t h0, l0, h1, l1;
    split2(res.x, res.y, h0, l0);
    split2(res.z, res.w, h1, l1);
    long long b = n * 64 + (j >> 1);
    hH[b] = h0; hH[b + 1] = h1;
    hL[b] = l0; hL[b + 1] = l1;
}

// ---------------- pooling + head ----------------------------------------------
__global__ void pool_kernel(const float* __restrict__ h,
                            const int* __restrict__ batch,
                            float* __restrict__ sums, float* __restrict__ cnt,
                            int Nn) {
    long long idx = (long long)blockIdx.x * blockDim.x + threadIdx.x;
    if (idx >= (long long)Nn * HID) return;
    long long n = idx >> 7;
    int j = (int)(idx & 127);
    int b = batch[n];
    atomicAdd(&sums[b * HID + j], h[idx]);
    if (j == 0) atomicAdd(&cnt[b], 1.0f);
}

__global__ void final_kernel(const float* __restrict__ sums,
                             const float* __restrict__ cnt,
                             const float* __restrict__ w_pred,
                             const float* __restrict__ b_pred,
                             float* __restrict__ out) {
    int g = blockIdx.x;
    int t = threadIdx.x;   // 128
    float c = fmaxf(cnt[g], 1.0f);
    float v = fmaxf(sums[g * HID + t] / c, 0.0f) * w_pred[t];
#pragma unroll
    for (int o = 16; o > 0; o >>= 1) v += __shfl_down_sync(0xffffffffu, v, o);
    __shared__ float ws[4];
    if ((t & 31) == 0) ws[t >> 5] = v;
    __syncthreads();
    if (t == 0) out[g] = ws[0] + ws[1] + ws[2] + ws[3] + b_pred[0];
}

// ---------------- host launcher -----------------------------------------------
extern "C" void kernel_launch(void* const* d_in, const int* in_sizes, int n_in,
                              void* d_out, int out_size) {
    const float* x       = (const float*)d_in[0];
    const int*   ei      = (const int*)d_in[1];
    const int*   batch   = (const int*)d_in[2];
    const float* W_embed = (const float*)d_in[3];
    const float* W_mpnn  = (const float*)d_in[4];
    const float* w_ih    = (const float*)d_in[5];
    const float* w_hh    = (const float*)d_in[6];
    const float* b_ih    = (const float*)d_in[7];
    const float* b_hh    = (const float*)d_in[8];
    const float* w_pred  = (const float*)d_in[9];
    const float* b_pred  = (const float*)d_in[10];
    float* out = (float*)d_out;

    int Nn = in_sizes[2];
    long long E = in_sizes[1] / 2;
    int steps = in_sizes[4] / (HID * HID);
    int F  = in_sizes[0] / Nn;      // 92
    int G = out_size;
    int KPx = F / 2;                 // 46
    int Apx = (KPx + 15) & ~15;      // 48

    float *p_h, *p_out1, *p_gi, *p_sums, *p_cnt;
    uint32_t *p_hH, *p_hL, *p_aggH, *p_aggL, *p_xH, *p_xL;
    uint32_t *p_WcatH, *p_WcatL, *p_WihTH, *p_WihTL, *p_WembH, *p_WembL;
    int *p_deg, *p_rowptr, *p_cursor, *p_esrc;
    cudaGetSymbolAddress((void**)&p_h,     g_h);
    cudaGetSymbolAddress((void**)&p_out1,  g_out1);
    cudaGetSymbolAddress((void**)&p_gi,    g_gi);
    cudaGetSymbolAddress((void**)&p_hH,    g_hH);
    cudaGetSymbolAddress((void**)&p_hL,    g_hL);
    cudaGetSymbolAddress((void**)&p_aggH,  g_aggH);
    cudaGetSymbolAddress((void**)&p_aggL,  g_aggL);
    cudaGetSymbolAddress((void**)&p_xH,    g_xH);
    cudaGetSymbolAddress((void**)&p_xL,    g_xL);
    cudaGetSymbolAddress((void**)&p_WcatH, g_WcatH);
    cudaGetSymbolAddress((void**)&p_WcatL, g_WcatL);
    cudaGetSymbolAddress((void**)&p_WihTH, g_WihTH);
    cudaGetSymbolAddress((void**)&p_WihTL, g_WihTL);
    cudaGetSymbolAddress((void**)&p_WembH, g_WembH);
    cudaGetSymbolAddress((void**)&p_WembL, g_WembL);
    cudaGetSymbolAddress((void**)&p_deg,   g_deg);
    cudaGetSymbolAddress((void**)&p_rowptr,g_rowptr);
    cudaGetSymbolAddress((void**)&p_cursor,g_cursor);
    cudaGetSymbolAddress((void**)&p_esrc,  g_esrc);
    cudaGetSymbolAddress((void**)&p_sums,  g_sums);
    cudaGetSymbolAddress((void**)&p_cnt,   g_cnt);

    // ---- weight & input pre-split ----
    {
        int total = steps * 64 * 512;
        pack_wcat_kernel<<<(total + 255) / 256, 256>>>(W_mpnn, w_hh, p_WcatH, p_WcatL, steps);
        pack_wihT_kernel<<<(64 * 384 + 255) / 256, 256>>>(w_ih, p_WihTH, p_WihTL);
        pack_wemb_kernel<<<(48 * 128 + 255) / 256, 256>>>(W_embed, p_WembH, p_WembL, KPx);
        long long tx = (long long)Nn * Apx;
        split_x_kernel<<<(int)((tx + 255) / 256), 256>>>(x, p_xH, p_xL, Nn, F, KPx, Apx);
    }

    // ---- CSR build ----
    zero_i<<<(Nn + 255) / 256, 256>>>(p_deg, Nn);
    hist_kernel<<<(int)((E + 255) / 256), 256>>>(ei, E, p_deg);
    scan_kernel<<<1, 1024>>>(p_deg, p_rowptr, p_cursor, Nn);
    fill_kernel<<<(int)((E + 255) / 256), 256>>>(ei, E, p_cursor, p_esrc);

    int mt = (Nn + 127) / 128;

    // ---- embed: h = tanh(x @ W_embed), also write hH/hL splits ----
    mma_gemm_kernel<<<dim3(1, mt), 256>>>(p_xH, p_xL, KPx, Apx,
                                          p_WembH, p_WembL,
                                          p_h, Nn, HID, nullptr, 0, 1,
                                          p_hH, p_hL, 64);

    long long nh = (long long)Nn * HID;

    for (int s = 0; s < steps; s++) {
        // [m | gh] = h @ [W_mpnn[s] | w_hh^T]  (+b_hh on gh cols)
        mma_gemm_kernel<<<dim3(4, mt), 256>>>(p_hH, p_hL, 64, 64,
                                              p_WcatH + (long long)s * 64 * 512,
                                              p_WcatL + (long long)s * 64 * 512,
                                              p_out1, Nn, 512, b_hh, HID, 0,
                                              nullptr, nullptr, 0);

        // agg = segment_sum(m[src], dst) via CSR gather; writes split agg
        gather_kernel<<<(int)(((long long)Nn * 32 + 255) / 256), 256>>>(
            p_rowptr, p_esrc, p_out1, p_aggH, p_aggL, Nn);

        // gi = agg @ w_ih^T + b_ih
        mma_gemm_kernel<<<dim3(3, mt), 256>>>(p_aggH, p_aggL, 64, 64,
                                              p_WihTH, p_WihTL,
                                              p_gi, Nn, 384, b_ih, 0, 0,
                                              nullptr, nullptr, 0);

        gate_kernel<<<(int)((nh / 4 + 255) / 256), 256>>>(p_gi, p_out1, p_h, p_hH, p_hL, Nn);
    }

    zero_f<<<(NG * HID + 255) / 256, 256>>>(p_sums, NG * HID);
    zero_f<<<1, 256>>>(p_cnt, NG);
    pool_kernel<<<(int)((nh + 255) / 256), 256>>>(p_h, batch, p_sums, p_cnt, Nn);
    final_kernel<<<G, HID>>>(p_sums, p_cnt, w_pred, b_pred, out);
}